// round 1
// baseline (speedup 1.0000x reference)
#include <cuda_runtime.h>
#include <cuda_bf16.h>
#include <math_constants.h>
#include <cstdint>

// Problem constants
#define BATCH 2
#define TLEN 2048
#define DMODEL 1024
#define NHEADS 16
#define NGROUPS 4
#define DK 64
#define WINDOW 512
#define MTOK (BATCH * TLEN)   // 4096

// -------- scratch (static device globals; no runtime allocation) --------
__device__ float g_Q[MTOK * DMODEL];        // 16 MB
__device__ float g_K[MTOK * NGROUPS * DK];  // 4 MB
__device__ float g_V[MTOK * NGROUPS * DK];  // 4 MB
__device__ float g_ATT[MTOK * DMODEL];      // 16 MB

// =======================================================================
// GEMM: C[M,N] = A[M,K] @ B[N,K]^T   (both A,B row-major, K contiguous)
// Tiles: BM=BN=64, BK=16, 256 threads, 4x4 register micro-tile.
// =======================================================================
__global__ __launch_bounds__(256) void gemm_abt(
    const float* __restrict__ A, const float* __restrict__ B,
    float* __restrict__ C, int M, int N, int K)
{
    __shared__ float as[16][68];  // as[k][m]
    __shared__ float bs[16][68];  // bs[k][n]

    const int n0 = blockIdx.x * 64;
    const int m0 = blockIdx.y * 64;
    const int tid = threadIdx.x;
    const int ty = tid >> 4;      // 0..15 (rows)
    const int tx = tid & 15;      // 0..15 (cols)

    float c[4][4];
#pragma unroll
    for (int i = 0; i < 4; i++)
#pragma unroll
        for (int j = 0; j < 4; j++) c[i][j] = 0.f;

    const int lrow = tid >> 2;          // 0..63
    const int lk   = (tid & 3) * 4;     // 0,4,8,12

    for (int k0 = 0; k0 < K; k0 += 16) {
        // load A tile (64x16) and B tile (64x16), transposed into smem
        float4 va = *(const float4*)(A + (size_t)(m0 + lrow) * K + k0 + lk);
        as[lk + 0][lrow] = va.x; as[lk + 1][lrow] = va.y;
        as[lk + 2][lrow] = va.z; as[lk + 3][lrow] = va.w;
        float4 vb = *(const float4*)(B + (size_t)(n0 + lrow) * K + k0 + lk);
        bs[lk + 0][lrow] = vb.x; bs[lk + 1][lrow] = vb.y;
        bs[lk + 2][lrow] = vb.z; bs[lk + 3][lrow] = vb.w;
        __syncthreads();

#pragma unroll
        for (int kk = 0; kk < 16; kk++) {
            float4 ra = *(const float4*)&as[kk][ty * 4];
            float4 rb = *(const float4*)&bs[kk][tx * 4];
            c[0][0] += ra.x * rb.x; c[0][1] += ra.x * rb.y; c[0][2] += ra.x * rb.z; c[0][3] += ra.x * rb.w;
            c[1][0] += ra.y * rb.x; c[1][1] += ra.y * rb.y; c[1][2] += ra.y * rb.z; c[1][3] += ra.y * rb.w;
            c[2][0] += ra.z * rb.x; c[2][1] += ra.z * rb.y; c[2][2] += ra.z * rb.z; c[2][3] += ra.z * rb.w;
            c[3][0] += ra.w * rb.x; c[3][1] += ra.w * rb.y; c[3][2] += ra.w * rb.z; c[3][3] += ra.w * rb.w;
        }
        __syncthreads();
    }

#pragma unroll
    for (int i = 0; i < 4; i++) {
        float* crow = C + (size_t)(m0 + ty * 4 + i) * N + n0 + tx * 4;
        float4 v = make_float4(c[i][0], c[i][1], c[i][2], c[i][3]);
        *(float4*)crow = v;
    }
}

// =======================================================================
// RoPE (interleaved pairs) applied in place.
// X layout: [tokens][heads*64]; one thread per (token, head, pair)
// =======================================================================
__global__ void rope_kernel(float* __restrict__ X, const int* __restrict__ pos,
                            int heads, int total)
{
    int idx = blockIdx.x * blockDim.x + threadIdx.x;
    if (idx >= total) return;
    int p = idx & 31;            // pair index 0..31
    int rest = idx >> 5;
    int h = rest % heads;
    int m = rest / heads;        // token row 0..4095
    int t = m & (TLEN - 1);      // token index within sequence

    float position = (float)pos[t];
    float inv = powf(10000.0f, -(float)p / 32.0f);
    float ang = position * inv;
    float c = cosf(ang), s = sinf(ang);

    float* base = X + (size_t)m * (heads * DK) + h * DK + 2 * p;
    float x1 = base[0], x2 = base[1];
    base[0] = x1 * c - x2 * s;
    base[1] = x1 * s + x2 * c;
}

// =======================================================================
// Sliding-window causal GQA attention, flash-style online softmax.
// Block: 256 threads, handles (b, head, 64-query tile); key tiles of 32.
// Thread (r = tid/4, cq = tid%4): query row r, output dims cq*16..cq*16+15.
// =======================================================================
__global__ __launch_bounds__(256) void attn_kernel(
    const float* __restrict__ Q, const float* __restrict__ K,
    const float* __restrict__ V, float* __restrict__ O)
{
    __shared__ float qs[64][68];   // q rows (pre-scaled by 1/8)
    __shared__ float kts[64][36];  // kts[d][j]  (transposed K tile)
    __shared__ float vs[32][68];   // vs[j][d]
    __shared__ float ps[64][33];   // scores

    const int tid = threadIdx.x;
    const int q0 = blockIdx.x * 64;
    const int h = blockIdx.y;
    const int b = blockIdx.z;
    const int g = h >> 2;
    const int r = tid >> 2;
    const int cq = tid & 3;

    const float* Qb = Q + ((size_t)(b * TLEN + q0)) * DMODEL + h * DK;
    // load + scale Q tile (64x64)
#pragma unroll
    for (int it = 0; it < 4; it++) {
        int f = tid + it * 256;
        int row = f >> 4;
        int d = (f & 15) * 4;
        float4 v = *(const float4*)(Qb + (size_t)row * DMODEL + d);
        qs[row][d + 0] = v.x * 0.125f;
        qs[row][d + 1] = v.y * 0.125f;
        qs[row][d + 2] = v.z * 0.125f;
        qs[row][d + 3] = v.w * 0.125f;
    }
    __syncthreads();

    float m_i = -CUDART_INF_F, l_i = 0.f;
    float acc[16];
#pragma unroll
    for (int i = 0; i < 16; i++) acc[i] = 0.f;

    const int i_glob = q0 + r;
    int jmin = q0 - WINDOW;
    if (jmin < 0) jmin = 0;

    const float* Kb = K + ((size_t)b * TLEN) * (NGROUPS * DK) + g * DK;
    const float* Vb = V + ((size_t)b * TLEN) * (NGROUPS * DK) + g * DK;
    const int kvstride = NGROUPS * DK;  // 256

    for (int k0 = jmin; k0 < q0 + 64; k0 += 32) {
        // ---- load K (transposed) and V tiles: 32 rows x 64 dims each ----
#pragma unroll
        for (int it = 0; it < 2; it++) {
            int f = tid + it * 256;
            int jj = f >> 4;
            int d = (f & 15) * 4;
            float4 kv = *(const float4*)(Kb + (size_t)(k0 + jj) * kvstride + d);
            kts[d + 0][jj] = kv.x; kts[d + 1][jj] = kv.y;
            kts[d + 2][jj] = kv.z; kts[d + 3][jj] = kv.w;
            float4 vv = *(const float4*)(Vb + (size_t)(k0 + jj) * kvstride + d);
            *(float4*)&vs[jj][d] = vv;
        }
        __syncthreads();

        // ---- S = Q K^T for my (row r, 8 columns cq*8..cq*8+7) ----
        float s0[8];
#pragma unroll
        for (int j = 0; j < 8; j++) s0[j] = 0.f;
#pragma unroll
        for (int k = 0; k < 64; k++) {
            float qv = qs[r][k];
            float4 ka = *(const float4*)&kts[k][cq * 8];
            float4 kb = *(const float4*)&kts[k][cq * 8 + 4];
            s0[0] += qv * ka.x; s0[1] += qv * ka.y; s0[2] += qv * ka.z; s0[3] += qv * ka.w;
            s0[4] += qv * kb.x; s0[5] += qv * kb.y; s0[6] += qv * kb.z; s0[7] += qv * kb.w;
        }
#pragma unroll
        for (int j = 0; j < 8; j++) {
            int jg = k0 + cq * 8 + j;
            bool ok = (jg <= i_glob) && (i_glob - jg <= WINDOW);
            ps[r][cq * 8 + j] = ok ? s0[j] : -CUDART_INF_F;
        }
        __syncthreads();

        // ---- online softmax update + P·V (per-row, replicated x4) ----
        float tmax = -CUDART_INF_F;
#pragma unroll
        for (int j = 0; j < 32; j++) tmax = fmaxf(tmax, ps[r][j]);
        float m_new = fmaxf(m_i, tmax);
        if (m_new > -CUDART_INF_F) {
            float corr = expf(m_i - m_new);  // expf(-inf)=0, safe
            l_i *= corr;
#pragma unroll
            for (int i = 0; i < 16; i++) acc[i] *= corr;
            const int d0 = cq * 16;
#pragma unroll 4
            for (int j = 0; j < 32; j++) {
                float p = expf(ps[r][j] - m_new);  // masked -> exp(-inf)=0
                l_i += p;
                float4 v0 = *(const float4*)&vs[j][d0 + 0];
                float4 v1 = *(const float4*)&vs[j][d0 + 4];
                float4 v2 = *(const float4*)&vs[j][d0 + 8];
                float4 v3 = *(const float4*)&vs[j][d0 + 12];
                acc[0]  += p * v0.x; acc[1]  += p * v0.y; acc[2]  += p * v0.z; acc[3]  += p * v0.w;
                acc[4]  += p * v1.x; acc[5]  += p * v1.y; acc[6]  += p * v1.z; acc[7]  += p * v1.w;
                acc[8]  += p * v2.x; acc[9]  += p * v2.y; acc[10] += p * v2.z; acc[11] += p * v2.w;
                acc[12] += p * v3.x; acc[13] += p * v3.y; acc[14] += p * v3.z; acc[15] += p * v3.w;
            }
            m_i = m_new;
        }
        __syncthreads();
    }

    float inv_l = 1.0f / l_i;
    float* Ob = O + ((size_t)(b * TLEN + q0 + r)) * DMODEL + h * DK + cq * 16;
#pragma unroll
    for (int i = 0; i < 16; i += 4) {
        float4 v = make_float4(acc[i] * inv_l, acc[i + 1] * inv_l,
                               acc[i + 2] * inv_l, acc[i + 3] * inv_l);
        *(float4*)(Ob + i) = v;
    }
}

// =======================================================================
// Host launcher
// =======================================================================
extern "C" void kernel_launch(void* const* d_in, const int* in_sizes, int n_in,
                              void* d_out, int out_size)
{
    const float* x  = (const float*)d_in[0];
    const float* WQ = (const float*)d_in[1];
    const float* WK = (const float*)d_in[2];
    const float* WV = (const float*)d_in[3];
    const float* WO = (const float*)d_in[4];
    const int* tpos = (const int*)d_in[5];
    float* out = (float*)d_out;

    float *Qp, *Kp, *Vp, *Ap;
    cudaGetSymbolAddress((void**)&Qp, g_Q);
    cudaGetSymbolAddress((void**)&Kp, g_K);
    cudaGetSymbolAddress((void**)&Vp, g_V);
    cudaGetSymbolAddress((void**)&Ap, g_ATT);

    // 1. Projections
    gemm_abt<<<dim3(DMODEL / 64, MTOK / 64), 256>>>(x, WQ, Qp, MTOK, DMODEL, DMODEL);
    gemm_abt<<<dim3((NGROUPS * DK) / 64, MTOK / 64), 256>>>(x, WK, Kp, MTOK, NGROUPS * DK, DMODEL);
    gemm_abt<<<dim3((NGROUPS * DK) / 64, MTOK / 64), 256>>>(x, WV, Vp, MTOK, NGROUPS * DK, DMODEL);

    // 2. RoPE
    {
        int totalq = MTOK * NHEADS * 32;
        rope_kernel<<<(totalq + 255) / 256, 256>>>(Qp, tpos, NHEADS, totalq);
        int totalk = MTOK * NGROUPS * 32;
        rope_kernel<<<(totalk + 255) / 256, 256>>>(Kp, tpos, NGROUPS, totalk);
    }

    // 3. Attention
    attn_kernel<<<dim3(TLEN / 64, NHEADS, BATCH), 256>>>(Qp, Kp, Vp, Ap);

    // 4. Output projection
    gemm_abt<<<dim3(DMODEL / 64, MTOK / 64), 256>>>(Ap, WO, out, MTOK, DMODEL, DMODEL);
}

// round 3
// speedup vs baseline: 1.3310x; 1.3310x over previous
#include <cuda_runtime.h>
#include <cuda_bf16.h>
#include <math_constants.h>
#include <cstdint>

// Problem constants
#define BATCH 2
#define TLEN 2048
#define DMODEL 1024
#define NHEADS 16
#define NGROUPS 4
#define DK 64
#define WINDOW 512
#define MTOK (BATCH * TLEN)   // 4096

// -------- scratch (static device globals; no runtime allocation) --------
__device__ float g_Q[MTOK * DMODEL];        // 16 MB
__device__ float g_K[MTOK * NGROUPS * DK];  // 4 MB
__device__ float g_V[MTOK * NGROUPS * DK];  // 4 MB
__device__ float g_ATT[MTOK * DMODEL];      // 16 MB

// =======================================================================
// TF32 tensor-core GEMM: C[M,N] = A[M,K] @ B[N,K]^T  (row-major, K contig)
// BM=128, BN=64, BK=32; 256 threads = 8 warps in 4(m) x 2(n);
// warp tile 32x32 via m16n8k8 mma (2 m-tiles x 4 n-tiles).
// =======================================================================
#define BM 128
#define BN 64
#define BK 32
#define SPAD 36   // padded row stride (words) -> conflict-free fragment loads

__device__ __forceinline__ uint32_t f2tf32(float f) {
    uint32_t u;
    asm volatile("cvt.rna.tf32.f32 %0, %1;" : "=r"(u) : "f"(f));
    return u;
}

__device__ __forceinline__ void mma_tf32(
    float& d0, float& d1, float& d2, float& d3,
    uint32_t a0, uint32_t a1, uint32_t a2, uint32_t a3,
    uint32_t b0, uint32_t b1)
{
    asm volatile(
        "mma.sync.aligned.m16n8k8.row.col.f32.tf32.tf32.f32 "
        "{%0,%1,%2,%3}, {%4,%5,%6,%7}, {%8,%9}, {%0,%1,%2,%3};\n"
        : "+f"(d0), "+f"(d1), "+f"(d2), "+f"(d3)
        : "r"(a0), "r"(a1), "r"(a2), "r"(a3), "r"(b0), "r"(b1));
}

__global__ __launch_bounds__(256) void gemm_tf32(
    const float* __restrict__ A, const float* __restrict__ B,
    float* __restrict__ C, int M, int N, int K)
{
    __shared__ uint32_t As[BM][SPAD];
    __shared__ uint32_t Bs[BN][SPAD];

    const int tid  = threadIdx.x;
    const int warp = tid >> 5;
    const int lane = tid & 31;
    const int wm0  = (warp >> 1) * 32;   // warp m-origin (0,32,64,96)
    const int wn0  = (warp & 1) * 32;    // warp n-origin (0,32)
    const int m0   = blockIdx.y * BM;
    const int n0   = blockIdx.x * BN;

    const int r  = lane >> 2;   // 0..7
    const int cl = lane & 3;    // 0..3

    float c[2][4][4];
#pragma unroll
    for (int mt = 0; mt < 2; mt++)
#pragma unroll
        for (int nt = 0; nt < 4; nt++)
#pragma unroll
            for (int i = 0; i < 4; i++) c[mt][nt][i] = 0.f;

    const int lrow = tid >> 3;        // 0..31
    const int lcol = (tid & 7) * 4;   // 0..28

    for (int k0 = 0; k0 < K; k0 += BK) {
        // ---- stage A (128x32) and B (64x32), converting to tf32 ----
#pragma unroll
        for (int p = 0; p < 4; p++) {
            float4 v = *(const float4*)(A + (size_t)(m0 + p * 32 + lrow) * K + k0 + lcol);
            uint4 t = make_uint4(f2tf32(v.x), f2tf32(v.y), f2tf32(v.z), f2tf32(v.w));
            *(uint4*)&As[p * 32 + lrow][lcol] = t;
        }
#pragma unroll
        for (int p = 0; p < 2; p++) {
            float4 v = *(const float4*)(B + (size_t)(n0 + p * 32 + lrow) * K + k0 + lcol);
            uint4 t = make_uint4(f2tf32(v.x), f2tf32(v.y), f2tf32(v.z), f2tf32(v.w));
            *(uint4*)&Bs[p * 32 + lrow][lcol] = t;
        }
        __syncthreads();

        // ---- 4 k-steps of 8 ----
#pragma unroll
        for (int kk = 0; kk < BK; kk += 8) {
            uint32_t af[2][4], bf[4][2];
#pragma unroll
            for (int mt = 0; mt < 2; mt++) {
                af[mt][0] = As[wm0 + mt * 16 + r][kk + cl];
                af[mt][1] = As[wm0 + mt * 16 + r + 8][kk + cl];
                af[mt][2] = As[wm0 + mt * 16 + r][kk + cl + 4];
                af[mt][3] = As[wm0 + mt * 16 + r + 8][kk + cl + 4];
            }
#pragma unroll
            for (int nt = 0; nt < 4; nt++) {
                bf[nt][0] = Bs[wn0 + nt * 8 + r][kk + cl];
                bf[nt][1] = Bs[wn0 + nt * 8 + r][kk + cl + 4];
            }
#pragma unroll
            for (int mt = 0; mt < 2; mt++)
#pragma unroll
                for (int nt = 0; nt < 4; nt++)
                    mma_tf32(c[mt][nt][0], c[mt][nt][1], c[mt][nt][2], c[mt][nt][3],
                             af[mt][0], af[mt][1], af[mt][2], af[mt][3],
                             bf[nt][0], bf[nt][1]);
        }
        __syncthreads();
    }

    // ---- epilogue: per mma tile, c0/c1 -> row r, c2/c3 -> row r+8 ----
#pragma unroll
    for (int mt = 0; mt < 2; mt++) {
#pragma unroll
        for (int nt = 0; nt < 4; nt++) {
            int row = m0 + wm0 + mt * 16 + r;
            int col = n0 + wn0 + nt * 8 + 2 * cl;
            *(float2*)(C + (size_t)row * N + col) =
                make_float2(c[mt][nt][0], c[mt][nt][1]);
            *(float2*)(C + (size_t)(row + 8) * N + col) =
                make_float2(c[mt][nt][2], c[mt][nt][3]);
        }
    }
}

// =======================================================================
// RoPE (interleaved pairs) applied in place.
// =======================================================================
__global__ void rope_kernel(float* __restrict__ X, const int* __restrict__ pos,
                            int heads, int total)
{
    int idx = blockIdx.x * blockDim.x + threadIdx.x;
    if (idx >= total) return;
    int p = idx & 31;            // pair index 0..31
    int rest = idx >> 5;
    int h = rest % heads;
    int m = rest / heads;        // token row
    int t = m & (TLEN - 1);

    float position = (float)pos[t];
    const float l2t = 13.287712379549449f;  // log2(10000)
    float inv = exp2f(-(float)p * (l2t / 32.0f));
    float ang = position * inv;
    float c, s;
    sincosf(ang, &s, &c);

    float* base = X + (size_t)m * (heads * DK) + h * DK + 2 * p;
    float x1 = base[0], x2 = base[1];
    base[0] = x1 * c - x2 * s;
    base[1] = x1 * s + x2 * c;
}

// =======================================================================
// Sliding-window causal GQA attention, flash-style online softmax (fp32 SIMT)
// =======================================================================
__global__ __launch_bounds__(256) void attn_kernel(
    const float* __restrict__ Q, const float* __restrict__ K,
    const float* __restrict__ V, float* __restrict__ O)
{
    __shared__ float qs[64][68];
    __shared__ float kts[64][36];
    __shared__ float vs[32][68];
    __shared__ float ps[64][33];

    const int tid = threadIdx.x;
    const int q0 = blockIdx.x * 64;
    const int h = blockIdx.y;
    const int b = blockIdx.z;
    const int g = h >> 2;
    const int r = tid >> 2;
    const int cq = tid & 3;

    const float* Qb = Q + ((size_t)(b * TLEN + q0)) * DMODEL + h * DK;
#pragma unroll
    for (int it = 0; it < 4; it++) {
        int f = tid + it * 256;
        int row = f >> 4;
        int d = (f & 15) * 4;
        float4 v = *(const float4*)(Qb + (size_t)row * DMODEL + d);
        qs[row][d + 0] = v.x * 0.125f;
        qs[row][d + 1] = v.y * 0.125f;
        qs[row][d + 2] = v.z * 0.125f;
        qs[row][d + 3] = v.w * 0.125f;
    }
    __syncthreads();

    float m_i = -CUDART_INF_F, l_i = 0.f;
    float acc[16];
#pragma unroll
    for (int i = 0; i < 16; i++) acc[i] = 0.f;

    const int i_glob = q0 + r;
    int jmin = q0 - WINDOW;
    if (jmin < 0) jmin = 0;

    const float* Kb = K + ((size_t)b * TLEN) * (NGROUPS * DK) + g * DK;
    const float* Vb = V + ((size_t)b * TLEN) * (NGROUPS * DK) + g * DK;
    const int kvstride = NGROUPS * DK;  // 256

    for (int k0 = jmin; k0 < q0 + 64; k0 += 32) {
#pragma unroll
        for (int it = 0; it < 2; it++) {
            int f = tid + it * 256;
            int jj = f >> 4;
            int d = (f & 15) * 4;
            float4 kv = *(const float4*)(Kb + (size_t)(k0 + jj) * kvstride + d);
            kts[d + 0][jj] = kv.x; kts[d + 1][jj] = kv.y;
            kts[d + 2][jj] = kv.z; kts[d + 3][jj] = kv.w;
            float4 vv = *(const float4*)(Vb + (size_t)(k0 + jj) * kvstride + d);
            *(float4*)&vs[jj][d] = vv;
        }
        __syncthreads();

        float s0[8];
#pragma unroll
        for (int j = 0; j < 8; j++) s0[j] = 0.f;
#pragma unroll
        for (int k = 0; k < 64; k++) {
            float qv = qs[r][k];
            float4 ka = *(const float4*)&kts[k][cq * 8];
            float4 kb = *(const float4*)&kts[k][cq * 8 + 4];
            s0[0] += qv * ka.x; s0[1] += qv * ka.y; s0[2] += qv * ka.z; s0[3] += qv * ka.w;
            s0[4] += qv * kb.x; s0[5] += qv * kb.y; s0[6] += qv * kb.z; s0[7] += qv * kb.w;
        }
#pragma unroll
        for (int j = 0; j < 8; j++) {
            int jg = k0 + cq * 8 + j;
            bool ok = (jg <= i_glob) && (i_glob - jg <= WINDOW);
            ps[r][cq * 8 + j] = ok ? s0[j] : -CUDART_INF_F;
        }
        __syncthreads();

        float tmax = -CUDART_INF_F;
#pragma unroll
        for (int j = 0; j < 32; j++) tmax = fmaxf(tmax, ps[r][j]);
        float m_new = fmaxf(m_i, tmax);
        if (m_new > -CUDART_INF_F) {
            float corr = __expf(m_i - m_new);  // __expf(-inf)=0
            l_i *= corr;
#pragma unroll
            for (int i = 0; i < 16; i++) acc[i] *= corr;
            const int d0 = cq * 16;
#pragma unroll 4
            for (int j = 0; j < 32; j++) {
                float p = __expf(ps[r][j] - m_new);
                l_i += p;
                float4 v0 = *(const float4*)&vs[j][d0 + 0];
                float4 v1 = *(const float4*)&vs[j][d0 + 4];
                float4 v2 = *(const float4*)&vs[j][d0 + 8];
                float4 v3 = *(const float4*)&vs[j][d0 + 12];
                acc[0]  += p * v0.x; acc[1]  += p * v0.y; acc[2]  += p * v0.z; acc[3]  += p * v0.w;
                acc[4]  += p * v1.x; acc[5]  += p * v1.y; acc[6]  += p * v1.z; acc[7]  += p * v1.w;
                acc[8]  += p * v2.x; acc[9]  += p * v2.y; acc[10] += p * v2.z; acc[11] += p * v2.w;
                acc[12] += p * v3.x; acc[13] += p * v3.y; acc[14] += p * v3.z; acc[15] += p * v3.w;
            }
            m_i = m_new;
        }
        __syncthreads();
    }

    float inv_l = 1.0f / l_i;
    float* Ob = O + ((size_t)(b * TLEN + q0 + r)) * DMODEL + h * DK + cq * 16;
#pragma unroll
    for (int i = 0; i < 16; i += 4) {
        float4 v = make_float4(acc[i] * inv_l, acc[i + 1] * inv_l,
                               acc[i + 2] * inv_l, acc[i + 3] * inv_l);
        *(float4*)(Ob + i) = v;
    }
}

// =======================================================================
// Host launcher
// =======================================================================
extern "C" void kernel_launch(void* const* d_in, const int* in_sizes, int n_in,
                              void* d_out, int out_size)
{
    const float* x  = (const float*)d_in[0];
    const float* WQ = (const float*)d_in[1];
    const float* WK = (const float*)d_in[2];
    const float* WV = (const float*)d_in[3];
    const float* WO = (const float*)d_in[4];
    const int* tpos = (const int*)d_in[5];
    float* out = (float*)d_out;

    float *Qp, *Kp, *Vp, *Ap;
    cudaGetSymbolAddress((void**)&Qp, g_Q);
    cudaGetSymbolAddress((void**)&Kp, g_K);
    cudaGetSymbolAddress((void**)&Vp, g_V);
    cudaGetSymbolAddress((void**)&Ap, g_ATT);

    // 1. Projections (TF32 tensor cores)
    gemm_tf32<<<dim3(DMODEL / BN, MTOK / BM), 256>>>(x, WQ, Qp, MTOK, DMODEL, DMODEL);
    gemm_tf32<<<dim3((NGROUPS * DK) / BN, MTOK / BM), 256>>>(x, WK, Kp, MTOK, NGROUPS * DK, DMODEL);
    gemm_tf32<<<dim3((NGROUPS * DK) / BN, MTOK / BM), 256>>>(x, WV, Vp, MTOK, NGROUPS * DK, DMODEL);

    // 2. RoPE
    {
        int totalq = MTOK * NHEADS * 32;
        rope_kernel<<<(totalq + 255) / 256, 256>>>(Qp, tpos, NHEADS, totalq);
        int totalk = MTOK * NGROUPS * 32;
        rope_kernel<<<(totalk + 255) / 256, 256>>>(Kp, tpos, NGROUPS, totalk);
    }

    // 3. Attention
    attn_kernel<<<dim3(TLEN / 64, NHEADS, BATCH), 256>>>(Qp, Kp, Vp, Ap);

    // 4. Output projection (TF32 tensor cores)
    gemm_tf32<<<dim3(DMODEL / BN, MTOK / BM), 256>>>(Ap, WO, out, MTOK, DMODEL, DMODEL);
}

// round 4
// speedup vs baseline: 3.8863x; 2.9199x over previous
#include <cuda_runtime.h>
#include <cuda_bf16.h>
#include <math_constants.h>
#include <cstdint>

// Problem constants
#define BATCH 2
#define TLEN 2048
#define DMODEL 1024
#define NHEADS 16
#define NGROUPS 4
#define DK 64
#define WINDOW 512
#define MTOK (BATCH * TLEN)   // 4096

// -------- scratch (static device globals; no runtime allocation) --------
__device__ float g_Q[MTOK * DMODEL];        // 16 MB
__device__ float g_K[MTOK * NGROUPS * DK];  // 4 MB
__device__ float g_V[MTOK * NGROUPS * DK];  // 4 MB
__device__ float g_ATT[MTOK * DMODEL];      // 16 MB

__device__ __forceinline__ uint32_t f2tf32(float f) {
    uint32_t u;
    asm volatile("cvt.rna.tf32.f32 %0, %1;" : "=r"(u) : "f"(f));
    return u;
}

__device__ __forceinline__ void mma_tf32(
    float& d0, float& d1, float& d2, float& d3,
    uint32_t a0, uint32_t a1, uint32_t a2, uint32_t a3,
    uint32_t b0, uint32_t b1)
{
    asm volatile(
        "mma.sync.aligned.m16n8k8.row.col.f32.tf32.tf32.f32 "
        "{%0,%1,%2,%3}, {%4,%5,%6,%7}, {%8,%9}, {%0,%1,%2,%3};\n"
        : "+f"(d0), "+f"(d1), "+f"(d2), "+f"(d3)
        : "r"(a0), "r"(a1), "r"(a2), "r"(a3), "r"(b0), "r"(b1));
}

// =======================================================================
// TF32 tensor-core GEMM with register prefetch:
// C[M,N] = A[M,K] @ B[N,K]^T ; BM=128 BN=64 BK=32; 8 warps, 32x32 per warp
// =======================================================================
#define BM 128
#define BN 64
#define BK 32
#define SPAD 36

__global__ __launch_bounds__(256) void gemm_tf32(
    const float* __restrict__ A, const float* __restrict__ B,
    float* __restrict__ C, int M, int N, int K)
{
    __shared__ uint32_t As[BM][SPAD];
    __shared__ uint32_t Bs[BN][SPAD];

    const int tid  = threadIdx.x;
    const int warp = tid >> 5;
    const int lane = tid & 31;
    const int wm0  = (warp >> 1) * 32;
    const int wn0  = (warp & 1) * 32;
    const int m0   = blockIdx.y * BM;
    const int n0   = blockIdx.x * BN;

    const int r  = lane >> 2;
    const int cl = lane & 3;

    float c[2][4][4];
#pragma unroll
    for (int mt = 0; mt < 2; mt++)
#pragma unroll
        for (int nt = 0; nt < 4; nt++)
#pragma unroll
            for (int i = 0; i < 4; i++) c[mt][nt][i] = 0.f;

    const int lrow = tid >> 3;
    const int lcol = (tid & 7) * 4;

    float4 av[4], bv[2];
    // prologue: prefetch tile 0
#pragma unroll
    for (int p = 0; p < 4; p++)
        av[p] = *(const float4*)(A + (size_t)(m0 + p * 32 + lrow) * K + lcol);
#pragma unroll
    for (int p = 0; p < 2; p++)
        bv[p] = *(const float4*)(B + (size_t)(n0 + p * 32 + lrow) * K + lcol);

    for (int k0 = 0; k0 < K; k0 += BK) {
        // commit prefetched regs to smem (tf32)
#pragma unroll
        for (int p = 0; p < 4; p++) {
            uint4 t = make_uint4(f2tf32(av[p].x), f2tf32(av[p].y), f2tf32(av[p].z), f2tf32(av[p].w));
            *(uint4*)&As[p * 32 + lrow][lcol] = t;
        }
#pragma unroll
        for (int p = 0; p < 2; p++) {
            uint4 t = make_uint4(f2tf32(bv[p].x), f2tf32(bv[p].y), f2tf32(bv[p].z), f2tf32(bv[p].w));
            *(uint4*)&Bs[p * 32 + lrow][lcol] = t;
        }
        __syncthreads();

        // prefetch next tile (overlaps with mma below)
        if (k0 + BK < K) {
#pragma unroll
            for (int p = 0; p < 4; p++)
                av[p] = *(const float4*)(A + (size_t)(m0 + p * 32 + lrow) * K + k0 + BK + lcol);
#pragma unroll
            for (int p = 0; p < 2; p++)
                bv[p] = *(const float4*)(B + (size_t)(n0 + p * 32 + lrow) * K + k0 + BK + lcol);
        }

#pragma unroll
        for (int kk = 0; kk < BK; kk += 8) {
            uint32_t af[2][4], bf[4][2];
#pragma unroll
            for (int mt = 0; mt < 2; mt++) {
                af[mt][0] = As[wm0 + mt * 16 + r][kk + cl];
                af[mt][1] = As[wm0 + mt * 16 + r + 8][kk + cl];
                af[mt][2] = As[wm0 + mt * 16 + r][kk + cl + 4];
                af[mt][3] = As[wm0 + mt * 16 + r + 8][kk + cl + 4];
            }
#pragma unroll
            for (int nt = 0; nt < 4; nt++) {
                bf[nt][0] = Bs[wn0 + nt * 8 + r][kk + cl];
                bf[nt][1] = Bs[wn0 + nt * 8 + r][kk + cl + 4];
            }
#pragma unroll
            for (int mt = 0; mt < 2; mt++)
#pragma unroll
                for (int nt = 0; nt < 4; nt++)
                    mma_tf32(c[mt][nt][0], c[mt][nt][1], c[mt][nt][2], c[mt][nt][3],
                             af[mt][0], af[mt][1], af[mt][2], af[mt][3],
                             bf[nt][0], bf[nt][1]);
        }
        __syncthreads();
    }

#pragma unroll
    for (int mt = 0; mt < 2; mt++) {
#pragma unroll
        for (int nt = 0; nt < 4; nt++) {
            int row = m0 + wm0 + mt * 16 + r;
            int col = n0 + wn0 + nt * 8 + 2 * cl;
            *(float2*)(C + (size_t)row * N + col) =
                make_float2(c[mt][nt][0], c[mt][nt][1]);
            *(float2*)(C + (size_t)(row + 8) * N + col) =
                make_float2(c[mt][nt][2], c[mt][nt][3]);
        }
    }
}

// =======================================================================
// RoPE (interleaved pairs) in place.
// =======================================================================
__global__ void rope_kernel(float* __restrict__ X, const int* __restrict__ pos,
                            int heads, int total)
{
    int idx = blockIdx.x * blockDim.x + threadIdx.x;
    if (idx >= total) return;
    int p = idx & 31;
    int rest = idx >> 5;
    int h = rest % heads;
    int m = rest / heads;
    int t = m & (TLEN - 1);

    float position = (float)pos[t];
    const float l2t = 13.287712379549449f;  // log2(10000)
    float inv = exp2f(-(float)p * (l2t / 32.0f));
    float ang = position * inv;
    float c, s;
    sincosf(ang, &s, &c);

    float* base = X + (size_t)m * (heads * DK) + h * DK + 2 * p;
    float x1 = base[0], x2 = base[1];
    base[0] = x1 * c - x2 * s;
    base[1] = x1 * s + x2 * c;
}

// =======================================================================
// Tensor-core flash attention (tf32 mma for QK^T and P*V).
// CTA: 256 threads (8 warps), 64 queries x one head. Key tiles of 32.
// Warp w: m-tile = w>>1 (rows 16*(w>>1)..+15), half = w&1.
//   S (64x32): warp covers cols half*16 + {0..15} (2 n-tiles of 8).
//   O (64x64): warp covers dims half*32 + {0..31} (4 n-tiles of 8).
// =======================================================================
#define NEGBIG (-1e30f)

__global__ __launch_bounds__(256) void attn_mma_kernel(
    const float* __restrict__ Q, const float* __restrict__ K,
    const float* __restrict__ V, float* __restrict__ O)
{
    __shared__ uint32_t qs[64][68];   // Q tf32 (scaled by 1/8): [row][d]
    __shared__ uint32_t ks[32][68];   // K tile tf32: [key][d]
    __shared__ uint32_t vts[64][36];  // V^T tile tf32: [d][key]
    __shared__ uint32_t ps[64][36];   // P tf32: [row][key]
    __shared__ float m_s[64], l_s[64];
    __shared__ float pmax[2][64], psum[2][64];

    const int tid  = threadIdx.x;
    const int warp = tid >> 5;
    const int lane = tid & 31;
    const int r    = lane >> 2;   // 0..7
    const int cl   = lane & 3;    // 0..3
    const int wm   = (warp >> 1) * 16;
    const int half = warp & 1;

    const int q0 = blockIdx.x * 64;
    const int h  = blockIdx.y;
    const int b  = blockIdx.z;
    const int g  = h >> 2;

    const float* Qb = Q + ((size_t)(b * TLEN + q0)) * DMODEL + h * DK;
    const float* Kb = K + ((size_t)b * TLEN) * (NGROUPS * DK) + g * DK;
    const float* Vb = V + ((size_t)b * TLEN) * (NGROUPS * DK) + g * DK;

    // ---- stage Q (scaled, tf32) ----
#pragma unroll
    for (int it = 0; it < 4; it++) {
        int f = tid + it * 256;
        int row = f >> 4;
        int d = (f & 15) * 4;
        float4 v = *(const float4*)(Qb + (size_t)row * DMODEL + d);
        uint4 t = make_uint4(f2tf32(v.x * 0.125f), f2tf32(v.y * 0.125f),
                             f2tf32(v.z * 0.125f), f2tf32(v.w * 0.125f));
        *(uint4*)&qs[row][d] = t;
    }
    if (tid < 64) { m_s[tid] = NEGBIG; l_s[tid] = 0.f; }

    float oc[4][4];
#pragma unroll
    for (int nt = 0; nt < 4; nt++)
#pragma unroll
        for (int i = 0; i < 4; i++) oc[nt][i] = 0.f;

    const int row0 = wm + r;
    const int row1 = wm + r + 8;
    const int i0 = q0 + row0;
    const int i1 = q0 + row1;
    int jmin = q0 - WINDOW;
    if (jmin < 0) jmin = 0;

    for (int k0 = jmin; k0 < q0 + 64; k0 += 32) {
        __syncthreads();  // prior PV reads of ks/vts/ps done before overwrite

        // ---- stage K tile [32 keys][64 d] (coalesced LDG, STS.128) ----
#pragma unroll
        for (int it = 0; it < 2; it++) {
            int f = tid + it * 256;
            int jj = f >> 4;
            int d = (f & 15) * 4;
            float4 v = *(const float4*)(Kb + (size_t)(k0 + jj) * (NGROUPS * DK) + d);
            uint4 t = make_uint4(f2tf32(v.x), f2tf32(v.y), f2tf32(v.z), f2tf32(v.w));
            *(uint4*)&ks[jj][d] = t;
        }
        // ---- stage V^T tile: warp-per-dim-group, lane-per-key (bank-clean) ----
#pragma unroll
        for (int it = 0; it < 2; it++) {
            int f = tid + it * 256;
            int jj = f & 31;
            int d = (f >> 5) * 4;
            float4 v = *(const float4*)(Vb + (size_t)(k0 + jj) * (NGROUPS * DK) + d);
            vts[d + 0][jj] = f2tf32(v.x);
            vts[d + 1][jj] = f2tf32(v.y);
            vts[d + 2][jj] = f2tf32(v.z);
            vts[d + 3][jj] = f2tf32(v.w);
        }
        __syncthreads();

        // ---- S = Q K^T (2 n-tiles per warp, 8 k-steps) ----
        float sc[2][4];
#pragma unroll
        for (int nt = 0; nt < 2; nt++)
#pragma unroll
            for (int i = 0; i < 4; i++) sc[nt][i] = 0.f;
#pragma unroll
        for (int kk = 0; kk < 8; kk++) {
            uint32_t a0 = qs[row0][kk * 8 + cl];
            uint32_t a1 = qs[row1][kk * 8 + cl];
            uint32_t a2 = qs[row0][kk * 8 + cl + 4];
            uint32_t a3 = qs[row1][kk * 8 + cl + 4];
#pragma unroll
            for (int nt = 0; nt < 2; nt++) {
                int nb = half * 16 + nt * 8 + r;
                uint32_t b0 = ks[nb][kk * 8 + cl];
                uint32_t b1 = ks[nb][kk * 8 + cl + 4];
                mma_tf32(sc[nt][0], sc[nt][1], sc[nt][2], sc[nt][3],
                         a0, a1, a2, a3, b0, b1);
            }
        }

        // ---- mask + partial row max ----
        float rmax0 = NEGBIG, rmax1 = NEGBIG;
#pragma unroll
        for (int nt = 0; nt < 2; nt++) {
            int jc = k0 + half * 16 + nt * 8 + 2 * cl;
#pragma unroll
            for (int e = 0; e < 2; e++) {      // e: column offset 0/1
                int j = jc + e;
                bool ok0 = (j <= i0) && (i0 - j <= WINDOW);
                bool ok1 = (j <= i1) && (i1 - j <= WINDOW);
                sc[nt][e]     = ok0 ? sc[nt][e]     : NEGBIG;
                sc[nt][e + 2] = ok1 ? sc[nt][e + 2] : NEGBIG;
                rmax0 = fmaxf(rmax0, sc[nt][e]);
                rmax1 = fmaxf(rmax1, sc[nt][e + 2]);
            }
        }
        rmax0 = fmaxf(rmax0, __shfl_xor_sync(0xffffffffu, rmax0, 1));
        rmax0 = fmaxf(rmax0, __shfl_xor_sync(0xffffffffu, rmax0, 2));
        rmax1 = fmaxf(rmax1, __shfl_xor_sync(0xffffffffu, rmax1, 1));
        rmax1 = fmaxf(rmax1, __shfl_xor_sync(0xffffffffu, rmax1, 2));
        if (cl == 0) { pmax[half][row0] = rmax0; pmax[half][row1] = rmax1; }
        __syncthreads();

        // ---- softmax phase B ----
        float m_old0 = m_s[row0], m_old1 = m_s[row1];
        float m_new0 = fmaxf(m_old0, fmaxf(pmax[0][row0], pmax[1][row0]));
        float m_new1 = fmaxf(m_old1, fmaxf(pmax[0][row1], pmax[1][row1]));
        float corr0 = __expf(m_old0 - m_new0);
        float corr1 = __expf(m_old1 - m_new1);

        float sum0 = 0.f, sum1 = 0.f;
#pragma unroll
        for (int nt = 0; nt < 2; nt++) {
            int cbase = half * 16 + nt * 8 + 2 * cl;
            float p0 = __expf(sc[nt][0] - m_new0);
            float p1 = __expf(sc[nt][1] - m_new0);
            float p2 = __expf(sc[nt][2] - m_new1);
            float p3 = __expf(sc[nt][3] - m_new1);
            sum0 += p0 + p1;
            sum1 += p2 + p3;
            ps[row0][cbase]     = f2tf32(p0);
            ps[row0][cbase + 1] = f2tf32(p1);
            ps[row1][cbase]     = f2tf32(p2);
            ps[row1][cbase + 1] = f2tf32(p3);
        }
        sum0 += __shfl_xor_sync(0xffffffffu, sum0, 1);
        sum0 += __shfl_xor_sync(0xffffffffu, sum0, 2);
        sum1 += __shfl_xor_sync(0xffffffffu, sum1, 1);
        sum1 += __shfl_xor_sync(0xffffffffu, sum1, 2);
        if (cl == 0) { psum[half][row0] = sum0; psum[half][row1] = sum1; }

        // rescale O accumulators
#pragma unroll
        for (int nt = 0; nt < 4; nt++) {
            oc[nt][0] *= corr0; oc[nt][1] *= corr0;
            oc[nt][2] *= corr1; oc[nt][3] *= corr1;
        }
        __syncthreads();

        // owner updates running m/l (one thread per row)
        if (half == 0 && cl == 0) {
            l_s[row0] = l_s[row0] * corr0 + psum[0][row0] + psum[1][row0];
            l_s[row1] = l_s[row1] * corr1 + psum[0][row1] + psum[1][row1];
            m_s[row0] = m_new0;
            m_s[row1] = m_new1;
        }

        // ---- O += P V (4 n-tiles per warp, 4 k-steps) ----
#pragma unroll
        for (int kk = 0; kk < 4; kk++) {
            uint32_t a0 = ps[row0][kk * 8 + cl];
            uint32_t a1 = ps[row1][kk * 8 + cl];
            uint32_t a2 = ps[row0][kk * 8 + cl + 4];
            uint32_t a3 = ps[row1][kk * 8 + cl + 4];
#pragma unroll
            for (int nt = 0; nt < 4; nt++) {
                int nb = half * 32 + nt * 8 + r;
                uint32_t b0 = vts[nb][kk * 8 + cl];
                uint32_t b1 = vts[nb][kk * 8 + cl + 4];
                mma_tf32(oc[nt][0], oc[nt][1], oc[nt][2], oc[nt][3],
                         a0, a1, a2, a3, b0, b1);
            }
        }
    }

    __syncthreads();
    float inv0 = 1.0f / l_s[row0];
    float inv1 = 1.0f / l_s[row1];
    float* Ob0 = O + ((size_t)(b * TLEN + i0)) * DMODEL + h * DK;
    float* Ob1 = O + ((size_t)(b * TLEN + i1)) * DMODEL + h * DK;
#pragma unroll
    for (int nt = 0; nt < 4; nt++) {
        int dcol = half * 32 + nt * 8 + 2 * cl;
        *(float2*)(Ob0 + dcol) = make_float2(oc[nt][0] * inv0, oc[nt][1] * inv0);
        *(float2*)(Ob1 + dcol) = make_float2(oc[nt][2] * inv1, oc[nt][3] * inv1);
    }
}

// =======================================================================
// Host launcher
// =======================================================================
extern "C" void kernel_launch(void* const* d_in, const int* in_sizes, int n_in,
                              void* d_out, int out_size)
{
    const float* x  = (const float*)d_in[0];
    const float* WQ = (const float*)d_in[1];
    const float* WK = (const float*)d_in[2];
    const float* WV = (const float*)d_in[3];
    const float* WO = (const float*)d_in[4];
    const int* tpos = (const int*)d_in[5];
    float* out = (float*)d_out;

    float *Qp, *Kp, *Vp, *Ap;
    cudaGetSymbolAddress((void**)&Qp, g_Q);
    cudaGetSymbolAddress((void**)&Kp, g_K);
    cudaGetSymbolAddress((void**)&Vp, g_V);
    cudaGetSymbolAddress((void**)&Ap, g_ATT);

    // 1. Projections (TF32 tensor cores)
    gemm_tf32<<<dim3(DMODEL / BN, MTOK / BM), 256>>>(x, WQ, Qp, MTOK, DMODEL, DMODEL);
    gemm_tf32<<<dim3((NGROUPS * DK) / BN, MTOK / BM), 256>>>(x, WK, Kp, MTOK, NGROUPS * DK, DMODEL);
    gemm_tf32<<<dim3((NGROUPS * DK) / BN, MTOK / BM), 256>>>(x, WV, Vp, MTOK, NGROUPS * DK, DMODEL);

    // 2. RoPE
    {
        int totalq = MTOK * NHEADS * 32;
        rope_kernel<<<(totalq + 255) / 256, 256>>>(Qp, tpos, NHEADS, totalq);
        int totalk = MTOK * NGROUPS * 32;
        rope_kernel<<<(totalk + 255) / 256, 256>>>(Kp, tpos, NGROUPS, totalk);
    }

    // 3. Attention (tensor cores)
    attn_mma_kernel<<<dim3(TLEN / 64, NHEADS, BATCH), 256>>>(Qp, Kp, Vp, Ap);

    // 4. Output projection (TF32 tensor cores)
    gemm_tf32<<<dim3(DMODEL / BN, MTOK / BM), 256>>>(Ap, WO, out, MTOK, DMODEL, DMODEL);
}

// round 5
// speedup vs baseline: 4.0600x; 1.0447x over previous
#include <cuda_runtime.h>
#include <cuda_bf16.h>
#include <math_constants.h>
#include <cstdint>

// Problem constants
#define BATCH 2
#define TLEN 2048
#define DMODEL 1024
#define NHEADS 16
#define NGROUPS 4
#define DK 64
#define WINDOW 512
#define MTOK (BATCH * TLEN)   // 4096

// -------- scratch (static device globals; no runtime allocation) --------
__device__ float g_Q[MTOK * DMODEL];        // 16 MB
__device__ float g_K[MTOK * NGROUPS * DK];  // 4 MB
__device__ float g_V[MTOK * NGROUPS * DK];  // 4 MB
__device__ float g_ATT[MTOK * DMODEL];      // 16 MB

__device__ __forceinline__ uint32_t f2tf32(float f) {
    uint32_t u;
    asm volatile("cvt.rna.tf32.f32 %0, %1;" : "=r"(u) : "f"(f));
    return u;
}

__device__ __forceinline__ void mma_tf32(
    float& d0, float& d1, float& d2, float& d3,
    uint32_t a0, uint32_t a1, uint32_t a2, uint32_t a3,
    uint32_t b0, uint32_t b1)
{
    asm volatile(
        "mma.sync.aligned.m16n8k8.row.col.f32.tf32.tf32.f32 "
        "{%0,%1,%2,%3}, {%4,%5,%6,%7}, {%8,%9}, {%0,%1,%2,%3};\n"
        : "+f"(d0), "+f"(d1), "+f"(d2), "+f"(d3)
        : "r"(a0), "r"(a1), "r"(a2), "r"(a3), "r"(b0), "r"(b1));
}

__device__ __forceinline__ void cp_async16(uint32_t saddr, const void* gptr) {
    asm volatile("cp.async.cg.shared.global [%0], [%1], 16;"
                 :: "r"(saddr), "l"(gptr));
}
__device__ __forceinline__ void cp_commit() {
    asm volatile("cp.async.commit_group;");
}
__device__ __forceinline__ void cp_wait_all() {
    asm volatile("cp.async.wait_group 0;");
}

// =======================================================================
// TF32 GEMM, cp.async double-buffered:
// C[M,N] = A[M,K] @ B[N,K]^T ; BM=128 BN=64 BK=32; 8 warps, 32x32/warp.
// blockIdx.z selects (B,C) pair -> fuses K/V projections in one launch.
// =======================================================================
#define BM 128
#define BN 64
#define BK 32
#define SPAD 36

__global__ __launch_bounds__(256) void gemm_tf32(
    const float* __restrict__ A,
    const float* __restrict__ B0, const float* __restrict__ B1,
    float* __restrict__ C0, float* __restrict__ C1,
    int M, int N, int K)
{
    extern __shared__ float gsm[];
    float (*As)[BM][SPAD] = (float(*)[BM][SPAD])gsm;
    float (*Bs)[BN][SPAD] = (float(*)[BN][SPAD])(gsm + 2 * BM * SPAD);

    const float* B = (blockIdx.z == 0) ? B0 : B1;
    float*       C = (blockIdx.z == 0) ? C0 : C1;

    const int tid  = threadIdx.x;
    const int warp = tid >> 5;
    const int lane = tid & 31;
    const int wm0  = (warp >> 1) * 32;
    const int wn0  = (warp & 1) * 32;
    const int m0   = blockIdx.y * BM;
    const int n0   = blockIdx.x * BN;

    const int r  = lane >> 2;
    const int cl = lane & 3;

    float c[2][4][4];
#pragma unroll
    for (int mt = 0; mt < 2; mt++)
#pragma unroll
        for (int nt = 0; nt < 4; nt++)
#pragma unroll
            for (int i = 0; i < 4; i++) c[mt][nt][i] = 0.f;

    const int lrow = tid >> 3;
    const int lcol = (tid & 7) * 4;

    // issue helper (stage buf, k-offset k0)
    auto issue = [&](int buf, int k0) {
#pragma unroll
        for (int p = 0; p < 4; p++)
            cp_async16((uint32_t)__cvta_generic_to_shared(&As[buf][p * 32 + lrow][lcol]),
                       A + (size_t)(m0 + p * 32 + lrow) * K + k0 + lcol);
#pragma unroll
        for (int p = 0; p < 2; p++)
            cp_async16((uint32_t)__cvta_generic_to_shared(&Bs[buf][p * 32 + lrow][lcol]),
                       B + (size_t)(n0 + p * 32 + lrow) * K + k0 + lcol);
        cp_commit();
    };

    issue(0, 0);
    int cur = 0;

    for (int k0 = 0; k0 < K; k0 += BK) {
        cp_wait_all();
        __syncthreads();
        if (k0 + BK < K) issue(cur ^ 1, k0 + BK);

#pragma unroll
        for (int kk = 0; kk < BK; kk += 8) {
            uint32_t af[2][4], bf[4][2];
#pragma unroll
            for (int mt = 0; mt < 2; mt++) {
                af[mt][0] = f2tf32(As[cur][wm0 + mt * 16 + r][kk + cl]);
                af[mt][1] = f2tf32(As[cur][wm0 + mt * 16 + r + 8][kk + cl]);
                af[mt][2] = f2tf32(As[cur][wm0 + mt * 16 + r][kk + cl + 4]);
                af[mt][3] = f2tf32(As[cur][wm0 + mt * 16 + r + 8][kk + cl + 4]);
            }
#pragma unroll
            for (int nt = 0; nt < 4; nt++) {
                bf[nt][0] = f2tf32(Bs[cur][wn0 + nt * 8 + r][kk + cl]);
                bf[nt][1] = f2tf32(Bs[cur][wn0 + nt * 8 + r][kk + cl + 4]);
            }
#pragma unroll
            for (int mt = 0; mt < 2; mt++)
#pragma unroll
                for (int nt = 0; nt < 4; nt++)
                    mma_tf32(c[mt][nt][0], c[mt][nt][1], c[mt][nt][2], c[mt][nt][3],
                             af[mt][0], af[mt][1], af[mt][2], af[mt][3],
                             bf[nt][0], bf[nt][1]);
        }
        cur ^= 1;
    }

#pragma unroll
    for (int mt = 0; mt < 2; mt++) {
#pragma unroll
        for (int nt = 0; nt < 4; nt++) {
            int row = m0 + wm0 + mt * 16 + r;
            int col = n0 + wn0 + nt * 8 + 2 * cl;
            *(float2*)(C + (size_t)row * N + col) =
                make_float2(c[mt][nt][0], c[mt][nt][1]);
            *(float2*)(C + (size_t)(row + 8) * N + col) =
                make_float2(c[mt][nt][2], c[mt][nt][3]);
        }
    }
}

// =======================================================================
// Fused RoPE for Q and K (interleaved pairs), in place.
// =======================================================================
#define NQ_ROPE (MTOK * NHEADS * 32)
#define NK_ROPE (MTOK * NGROUPS * 32)

__global__ void rope_all(float* __restrict__ Qx, float* __restrict__ Kx,
                         const int* __restrict__ pos)
{
    int idx = blockIdx.x * blockDim.x + threadIdx.x;
    float* X;
    int heads, local;
    if (idx < NQ_ROPE) { X = Qx; heads = NHEADS; local = idx; }
    else if (idx < NQ_ROPE + NK_ROPE) { X = Kx; heads = NGROUPS; local = idx - NQ_ROPE; }
    else return;

    int p = local & 31;
    int rest = local >> 5;
    int h = rest % heads;
    int m = rest / heads;
    int t = m & (TLEN - 1);

    float position = (float)pos[t];
    const float l2t = 13.287712379549449f;  // log2(10000)
    float inv = exp2f(-(float)p * (l2t / 32.0f));
    float ang = position * inv;
    float c, s;
    sincosf(ang, &s, &c);

    float* base = X + (size_t)m * (heads * DK) + h * DK + 2 * p;
    float x1 = base[0], x2 = base[1];
    base[0] = x1 * c - x2 * s;
    base[1] = x1 * s + x2 * c;
}

// =======================================================================
// Tensor-core flash attention, 64-query x 64-key tiles (tf32 mma).
// 8 warps: warp w -> rows 16*(w>>1)..+15, half=(w&1) -> col half 32-wide.
// Dynamic smem: qs,ks,vts,ps each [64][68] words.
// =======================================================================
#define NEGBIG (-1e30f)

__global__ __launch_bounds__(256) void attn_mma_kernel(
    const float* __restrict__ Q, const float* __restrict__ K,
    const float* __restrict__ V, float* __restrict__ O)
{
    extern __shared__ uint32_t asm_[];
    uint32_t (*qs)[68]  = (uint32_t(*)[68])asm_;
    uint32_t (*ks)[68]  = (uint32_t(*)[68])(asm_ + 64 * 68);
    uint32_t (*vts)[68] = (uint32_t(*)[68])(asm_ + 2 * 64 * 68);
    uint32_t (*ps)[68]  = (uint32_t(*)[68])(asm_ + 3 * 64 * 68);
    __shared__ float m_s[64], l_s[64];
    __shared__ float pmax[2][64], psum[2][64];

    const int tid  = threadIdx.x;
    const int warp = tid >> 5;
    const int lane = tid & 31;
    const int r    = lane >> 2;
    const int cl   = lane & 3;
    const int wm   = (warp >> 1) * 16;
    const int half = warp & 1;

    const int q0 = blockIdx.x * 64;
    const int h  = blockIdx.y;
    const int b  = blockIdx.z;
    const int g  = h >> 2;

    const float* Qb = Q + ((size_t)(b * TLEN + q0)) * DMODEL + h * DK;
    const float* Kb = K + ((size_t)b * TLEN) * (NGROUPS * DK) + g * DK;
    const float* Vb = V + ((size_t)b * TLEN) * (NGROUPS * DK) + g * DK;

    // ---- stage Q (scaled by 1/8, tf32) ----
#pragma unroll
    for (int it = 0; it < 4; it++) {
        int f = tid + it * 256;
        int row = f >> 4;
        int d = (f & 15) * 4;
        float4 v = *(const float4*)(Qb + (size_t)row * DMODEL + d);
        uint4 t = make_uint4(f2tf32(v.x * 0.125f), f2tf32(v.y * 0.125f),
                             f2tf32(v.z * 0.125f), f2tf32(v.w * 0.125f));
        *(uint4*)&qs[row][d] = t;
    }
    if (tid < 64) { m_s[tid] = NEGBIG; l_s[tid] = 0.f; }

    float oc[4][4];
#pragma unroll
    for (int nt = 0; nt < 4; nt++)
#pragma unroll
        for (int i = 0; i < 4; i++) oc[nt][i] = 0.f;

    const int row0 = wm + r;
    const int row1 = wm + r + 8;
    const int i0 = q0 + row0;
    const int i1 = q0 + row1;
    int jmin = q0 - WINDOW;
    if (jmin < 0) jmin = 0;

    for (int k0 = jmin; k0 < q0 + 64; k0 += 64) {
        __syncthreads();  // prior iteration's PV reads done before overwrite

        // ---- stage K tile [64 keys][64 d] ----
#pragma unroll
        for (int it = 0; it < 4; it++) {
            int f = tid + it * 256;
            int jj = f >> 4;
            int d = (f & 15) * 4;
            float4 v = *(const float4*)(Kb + (size_t)(k0 + jj) * (NGROUPS * DK) + d);
            uint4 t = make_uint4(f2tf32(v.x), f2tf32(v.y), f2tf32(v.z), f2tf32(v.w));
            *(uint4*)&ks[jj][d] = t;
        }
        // ---- stage V^T tile [64 d][64 keys] ----
#pragma unroll
        for (int it = 0; it < 4; it++) {
            int f = tid + it * 256;
            int jj = f & 63;
            int d = (f >> 6) * 4;
            float4 v = *(const float4*)(Vb + (size_t)(k0 + jj) * (NGROUPS * DK) + d);
            vts[d + 0][jj] = f2tf32(v.x);
            vts[d + 1][jj] = f2tf32(v.y);
            vts[d + 2][jj] = f2tf32(v.z);
            vts[d + 3][jj] = f2tf32(v.w);
        }
        __syncthreads();

        // ---- S = Q K^T (4 n-tiles per warp, 8 k-steps) ----
        float sc[4][4];
#pragma unroll
        for (int nt = 0; nt < 4; nt++)
#pragma unroll
            for (int i = 0; i < 4; i++) sc[nt][i] = 0.f;
#pragma unroll
        for (int kk = 0; kk < 8; kk++) {
            uint32_t a0 = qs[row0][kk * 8 + cl];
            uint32_t a1 = qs[row1][kk * 8 + cl];
            uint32_t a2 = qs[row0][kk * 8 + cl + 4];
            uint32_t a3 = qs[row1][kk * 8 + cl + 4];
#pragma unroll
            for (int nt = 0; nt < 4; nt++) {
                int nb = half * 32 + nt * 8 + r;
                uint32_t b0 = ks[nb][kk * 8 + cl];
                uint32_t b1 = ks[nb][kk * 8 + cl + 4];
                mma_tf32(sc[nt][0], sc[nt][1], sc[nt][2], sc[nt][3],
                         a0, a1, a2, a3, b0, b1);
            }
        }

        // ---- mask + partial row max ----
        float rmax0 = NEGBIG, rmax1 = NEGBIG;
#pragma unroll
        for (int nt = 0; nt < 4; nt++) {
            int jc = k0 + half * 32 + nt * 8 + 2 * cl;
#pragma unroll
            for (int e = 0; e < 2; e++) {
                int j = jc + e;
                bool ok0 = (j <= i0) && (i0 - j <= WINDOW);
                bool ok1 = (j <= i1) && (i1 - j <= WINDOW);
                sc[nt][e]     = ok0 ? sc[nt][e]     : NEGBIG;
                sc[nt][e + 2] = ok1 ? sc[nt][e + 2] : NEGBIG;
                rmax0 = fmaxf(rmax0, sc[nt][e]);
                rmax1 = fmaxf(rmax1, sc[nt][e + 2]);
            }
        }
        rmax0 = fmaxf(rmax0, __shfl_xor_sync(0xffffffffu, rmax0, 1));
        rmax0 = fmaxf(rmax0, __shfl_xor_sync(0xffffffffu, rmax0, 2));
        rmax1 = fmaxf(rmax1, __shfl_xor_sync(0xffffffffu, rmax1, 1));
        rmax1 = fmaxf(rmax1, __shfl_xor_sync(0xffffffffu, rmax1, 2));
        if (cl == 0) { pmax[half][row0] = rmax0; pmax[half][row1] = rmax1; }
        __syncthreads();

        // ---- softmax phase B ----
        float m_old0 = m_s[row0], m_old1 = m_s[row1];
        float m_new0 = fmaxf(m_old0, fmaxf(pmax[0][row0], pmax[1][row0]));
        float m_new1 = fmaxf(m_old1, fmaxf(pmax[0][row1], pmax[1][row1]));
        float corr0 = __expf(m_old0 - m_new0);
        float corr1 = __expf(m_old1 - m_new1);

        float sum0 = 0.f, sum1 = 0.f;
#pragma unroll
        for (int nt = 0; nt < 4; nt++) {
            int cbase = half * 32 + nt * 8 + 2 * cl;
            float p0 = __expf(sc[nt][0] - m_new0);
            float p1 = __expf(sc[nt][1] - m_new0);
            float p2 = __expf(sc[nt][2] - m_new1);
            float p3 = __expf(sc[nt][3] - m_new1);
            sum0 += p0 + p1;
            sum1 += p2 + p3;
            ps[row0][cbase]     = f2tf32(p0);
            ps[row0][cbase + 1] = f2tf32(p1);
            ps[row1][cbase]     = f2tf32(p2);
            ps[row1][cbase + 1] = f2tf32(p3);
        }
        sum0 += __shfl_xor_sync(0xffffffffu, sum0, 1);
        sum0 += __shfl_xor_sync(0xffffffffu, sum0, 2);
        sum1 += __shfl_xor_sync(0xffffffffu, sum1, 1);
        sum1 += __shfl_xor_sync(0xffffffffu, sum1, 2);
        if (cl == 0) { psum[half][row0] = sum0; psum[half][row1] = sum1; }

        // rescale O accumulators
#pragma unroll
        for (int nt = 0; nt < 4; nt++) {
            oc[nt][0] *= corr0; oc[nt][1] *= corr0;
            oc[nt][2] *= corr1; oc[nt][3] *= corr1;
        }
        __syncthreads();

        if (half == 0 && cl == 0) {
            l_s[row0] = l_s[row0] * corr0 + psum[0][row0] + psum[1][row0];
            l_s[row1] = l_s[row1] * corr1 + psum[0][row1] + psum[1][row1];
            m_s[row0] = m_new0;
            m_s[row1] = m_new1;
        }

        // ---- O += P V (4 n-tiles per warp, 8 k-steps) ----
#pragma unroll
        for (int kk = 0; kk < 8; kk++) {
            uint32_t a0 = ps[row0][kk * 8 + cl];
            uint32_t a1 = ps[row1][kk * 8 + cl];
            uint32_t a2 = ps[row0][kk * 8 + cl + 4];
            uint32_t a3 = ps[row1][kk * 8 + cl + 4];
#pragma unroll
            for (int nt = 0; nt < 4; nt++) {
                int nb = half * 32 + nt * 8 + r;
                uint32_t b0 = vts[nb][kk * 8 + cl];
                uint32_t b1 = vts[nb][kk * 8 + cl + 4];
                mma_tf32(oc[nt][0], oc[nt][1], oc[nt][2], oc[nt][3],
                         a0, a1, a2, a3, b0, b1);
            }
        }
    }

    __syncthreads();
    float inv0 = 1.0f / l_s[row0];
    float inv1 = 1.0f / l_s[row1];
    float* Ob0 = O + ((size_t)(b * TLEN + i0)) * DMODEL + h * DK;
    float* Ob1 = O + ((size_t)(b * TLEN + i1)) * DMODEL + h * DK;
#pragma unroll
    for (int nt = 0; nt < 4; nt++) {
        int dcol = half * 32 + nt * 8 + 2 * cl;
        *(float2*)(Ob0 + dcol) = make_float2(oc[nt][0] * inv0, oc[nt][1] * inv0);
        *(float2*)(Ob1 + dcol) = make_float2(oc[nt][2] * inv1, oc[nt][3] * inv1);
    }
}

// =======================================================================
// Host launcher
// =======================================================================
extern "C" void kernel_launch(void* const* d_in, const int* in_sizes, int n_in,
                              void* d_out, int out_size)
{
    const float* x  = (const float*)d_in[0];
    const float* WQ = (const float*)d_in[1];
    const float* WK = (const float*)d_in[2];
    const float* WV = (const float*)d_in[3];
    const float* WO = (const float*)d_in[4];
    const int* tpos = (const int*)d_in[5];
    float* out = (float*)d_out;

    float *Qp, *Kp, *Vp, *Ap;
    cudaGetSymbolAddress((void**)&Qp, g_Q);
    cudaGetSymbolAddress((void**)&Kp, g_K);
    cudaGetSymbolAddress((void**)&Vp, g_V);
    cudaGetSymbolAddress((void**)&Ap, g_ATT);

    const int gemm_smem = (2 * BM * SPAD + 2 * BN * SPAD) * 4;   // 55296 B
    const int attn_smem = 4 * 64 * 68 * 4;                        // 69632 B
    static bool attr_done = false;
    if (!attr_done) {
        cudaFuncSetAttribute(gemm_tf32, cudaFuncAttributeMaxDynamicSharedMemorySize, gemm_smem);
        cudaFuncSetAttribute(attn_mma_kernel, cudaFuncAttributeMaxDynamicSharedMemorySize, attn_smem);
        attr_done = true;
    }

    // 1. Q projection
    gemm_tf32<<<dim3(DMODEL / BN, MTOK / BM, 1), 256, gemm_smem>>>(
        x, WQ, WQ, Qp, Qp, MTOK, DMODEL, DMODEL);
    // 1b. K and V projections fused (blockIdx.z selects)
    gemm_tf32<<<dim3((NGROUPS * DK) / BN, MTOK / BM, 2), 256, gemm_smem>>>(
        x, WK, WV, Kp, Vp, MTOK, NGROUPS * DK, DMODEL);

    // 2. RoPE (Q and K in one launch)
    {
        int total = NQ_ROPE + NK_ROPE;
        rope_all<<<(total + 255) / 256, 256>>>(Qp, Kp, tpos);
    }

    // 3. Attention (tensor cores, 64x64 tiles)
    attn_mma_kernel<<<dim3(TLEN / 64, NHEADS, BATCH), 256, attn_smem>>>(Qp, Kp, Vp, Ap);

    // 4. Output projection
    gemm_tf32<<<dim3(DMODEL / BN, MTOK / BM, 1), 256, gemm_smem>>>(
        Ap, WO, WO, out, out, MTOK, DMODEL, DMODEL);
}

// round 6
// speedup vs baseline: 4.3253x; 1.0654x over previous
#include <cuda_runtime.h>
#include <cuda_bf16.h>
#include <math_constants.h>
#include <cstdint>

// Problem constants
#define BATCH 2
#define TLEN 2048
#define DMODEL 1024
#define NHEADS 16
#define NGROUPS 4
#define DK 64
#define WINDOW 512
#define MTOK (BATCH * TLEN)   // 4096

// -------- scratch (static device globals; no runtime allocation) --------
__device__ float g_Q[MTOK * DMODEL];        // 16 MB
__device__ float g_K[MTOK * NGROUPS * DK];  // 4 MB
__device__ float g_V[MTOK * NGROUPS * DK];  // 4 MB
__device__ float g_ATT[MTOK * DMODEL];      // 16 MB

__device__ __forceinline__ uint32_t f2tf32(float f) {
    uint32_t u;
    asm volatile("cvt.rna.tf32.f32 %0, %1;" : "=r"(u) : "f"(f));
    return u;
}

__device__ __forceinline__ void mma_tf32(
    float& d0, float& d1, float& d2, float& d3,
    uint32_t a0, uint32_t a1, uint32_t a2, uint32_t a3,
    uint32_t b0, uint32_t b1)
{
    asm volatile(
        "mma.sync.aligned.m16n8k8.row.col.f32.tf32.tf32.f32 "
        "{%0,%1,%2,%3}, {%4,%5,%6,%7}, {%8,%9}, {%0,%1,%2,%3};\n"
        : "+f"(d0), "+f"(d1), "+f"(d2), "+f"(d3)
        : "r"(a0), "r"(a1), "r"(a2), "r"(a3), "r"(b0), "r"(b1));
}

__device__ __forceinline__ void cp_async16(uint32_t saddr, const void* gptr) {
    asm volatile("cp.async.cg.shared.global [%0], [%1], 16;"
                 :: "r"(saddr), "l"(gptr));
}
__device__ __forceinline__ void cp_commit() {
    asm volatile("cp.async.commit_group;");
}
__device__ __forceinline__ void cp_wait_all() {
    asm volatile("cp.async.wait_group 0;");
}

// =======================================================================
// TF32 GEMM, cp.async double-buffered (unchanged from R5):
// C[M,N] = A[M,K] @ B[N,K]^T ; BM=128 BN=64 BK=32; 8 warps, 32x32/warp.
// =======================================================================
#define BM 128
#define BN 64
#define BK 32
#define SPAD 36

__global__ __launch_bounds__(256) void gemm_tf32(
    const float* __restrict__ A,
    const float* __restrict__ B0, const float* __restrict__ B1,
    float* __restrict__ C0, float* __restrict__ C1,
    int M, int N, int K)
{
    extern __shared__ float gsm[];
    float (*As)[BM][SPAD] = (float(*)[BM][SPAD])gsm;
    float (*Bs)[BN][SPAD] = (float(*)[BN][SPAD])(gsm + 2 * BM * SPAD);

    const float* B = (blockIdx.z == 0) ? B0 : B1;
    float*       C = (blockIdx.z == 0) ? C0 : C1;

    const int tid  = threadIdx.x;
    const int warp = tid >> 5;
    const int lane = tid & 31;
    const int wm0  = (warp >> 1) * 32;
    const int wn0  = (warp & 1) * 32;
    const int m0   = blockIdx.y * BM;
    const int n0   = blockIdx.x * BN;

    const int r  = lane >> 2;
    const int cl = lane & 3;

    float c[2][4][4];
#pragma unroll
    for (int mt = 0; mt < 2; mt++)
#pragma unroll
        for (int nt = 0; nt < 4; nt++)
#pragma unroll
            for (int i = 0; i < 4; i++) c[mt][nt][i] = 0.f;

    const int lrow = tid >> 3;
    const int lcol = (tid & 7) * 4;

    auto issue = [&](int buf, int k0) {
#pragma unroll
        for (int p = 0; p < 4; p++)
            cp_async16((uint32_t)__cvta_generic_to_shared(&As[buf][p * 32 + lrow][lcol]),
                       A + (size_t)(m0 + p * 32 + lrow) * K + k0 + lcol);
#pragma unroll
        for (int p = 0; p < 2; p++)
            cp_async16((uint32_t)__cvta_generic_to_shared(&Bs[buf][p * 32 + lrow][lcol]),
                       B + (size_t)(n0 + p * 32 + lrow) * K + k0 + lcol);
        cp_commit();
    };

    issue(0, 0);
    int cur = 0;

    for (int k0 = 0; k0 < K; k0 += BK) {
        cp_wait_all();
        __syncthreads();
        if (k0 + BK < K) issue(cur ^ 1, k0 + BK);

#pragma unroll
        for (int kk = 0; kk < BK; kk += 8) {
            uint32_t af[2][4], bf[4][2];
#pragma unroll
            for (int mt = 0; mt < 2; mt++) {
                af[mt][0] = f2tf32(As[cur][wm0 + mt * 16 + r][kk + cl]);
                af[mt][1] = f2tf32(As[cur][wm0 + mt * 16 + r + 8][kk + cl]);
                af[mt][2] = f2tf32(As[cur][wm0 + mt * 16 + r][kk + cl + 4]);
                af[mt][3] = f2tf32(As[cur][wm0 + mt * 16 + r + 8][kk + cl + 4]);
            }
#pragma unroll
            for (int nt = 0; nt < 4; nt++) {
                bf[nt][0] = f2tf32(Bs[cur][wn0 + nt * 8 + r][kk + cl]);
                bf[nt][1] = f2tf32(Bs[cur][wn0 + nt * 8 + r][kk + cl + 4]);
            }
#pragma unroll
            for (int mt = 0; mt < 2; mt++)
#pragma unroll
                for (int nt = 0; nt < 4; nt++)
                    mma_tf32(c[mt][nt][0], c[mt][nt][1], c[mt][nt][2], c[mt][nt][3],
                             af[mt][0], af[mt][1], af[mt][2], af[mt][3],
                             bf[nt][0], bf[nt][1]);
        }
        cur ^= 1;
    }

#pragma unroll
    for (int mt = 0; mt < 2; mt++) {
#pragma unroll
        for (int nt = 0; nt < 4; nt++) {
            int row = m0 + wm0 + mt * 16 + r;
            int col = n0 + wn0 + nt * 8 + 2 * cl;
            *(float2*)(C + (size_t)row * N + col) =
                make_float2(c[mt][nt][0], c[mt][nt][1]);
            *(float2*)(C + (size_t)(row + 8) * N + col) =
                make_float2(c[mt][nt][2], c[mt][nt][3]);
        }
    }
}

// =======================================================================
// Fused RoPE for Q and K (interleaved pairs), in place.
// =======================================================================
#define NQ_ROPE (MTOK * NHEADS * 32)
#define NK_ROPE (MTOK * NGROUPS * 32)

__global__ void rope_all(float* __restrict__ Qx, float* __restrict__ Kx,
                         const int* __restrict__ pos)
{
    int idx = blockIdx.x * blockDim.x + threadIdx.x;
    float* X;
    int heads, local;
    if (idx < NQ_ROPE) { X = Qx; heads = NHEADS; local = idx; }
    else if (idx < NQ_ROPE + NK_ROPE) { X = Kx; heads = NGROUPS; local = idx - NQ_ROPE; }
    else return;

    int p = local & 31;
    int rest = local >> 5;
    int h = rest % heads;
    int m = rest / heads;
    int t = m & (TLEN - 1);

    float position = (float)pos[t];
    const float l2t = 13.287712379549449f;  // log2(10000)
    float inv = exp2f(-(float)p * (l2t / 32.0f));
    float ang = position * inv;
    float c, s;
    sincosf(ang, &s, &c);

    float* base = X + (size_t)m * (heads * DK) + h * DK + 2 * p;
    float x1 = base[0], x2 = base[1];
    base[0] = x1 * c - x2 * s;
    base[1] = x1 * s + x2 * c;
}

// =======================================================================
// Tensor-core flash attention v2: 128-query x 64-key tiles.
// 8 warps; warp w owns rows [16w, 16w+16) completely (all 64 key cols,
// all 64 output dims). Softmax entirely warp-local: m/l in registers,
// quad shuffles for row reductions, shuffle-based C->A fragment
// conversion for P (no ps smem, no cross-warp barriers).
// Dynamic smem: qs[128][68], ks[64][68], vts[64][68] = 69632 B.
// =======================================================================
#define NEGBIG (-1e30f)
#define FULLM 0xffffffffu

__global__ __launch_bounds__(256) void attn_mma_kernel(
    const float* __restrict__ Q, const float* __restrict__ K,
    const float* __restrict__ V, float* __restrict__ O)
{
    extern __shared__ uint32_t asm_[];
    uint32_t (*qs)[68]  = (uint32_t(*)[68])asm_;
    uint32_t (*ks)[68]  = (uint32_t(*)[68])(asm_ + 128 * 68);
    uint32_t (*vts)[68] = (uint32_t(*)[68])(asm_ + 128 * 68 + 64 * 68);

    const int tid  = threadIdx.x;
    const int warp = tid >> 5;
    const int lane = tid & 31;
    const int r    = lane >> 2;   // 0..7
    const int cl   = lane & 3;    // 0..3

    const int q0 = blockIdx.x * 128;
    const int h  = blockIdx.y;
    const int b  = blockIdx.z;
    const int g  = h >> 2;

    const float* Qb = Q + ((size_t)(b * TLEN + q0)) * DMODEL + h * DK;
    const float* Kb = K + ((size_t)b * TLEN) * (NGROUPS * DK) + g * DK;
    const float* Vb = V + ((size_t)b * TLEN) * (NGROUPS * DK) + g * DK;

    // ---- stage Q (128x64, scaled by 1/8, tf32) ----
#pragma unroll
    for (int it = 0; it < 8; it++) {
        int f = tid + it * 256;
        int row = f >> 4;
        int d = (f & 15) * 4;
        float4 v = *(const float4*)(Qb + (size_t)row * DMODEL + d);
        uint4 t = make_uint4(f2tf32(v.x * 0.125f), f2tf32(v.y * 0.125f),
                             f2tf32(v.z * 0.125f), f2tf32(v.w * 0.125f));
        *(uint4*)&qs[row][d] = t;
    }

    const int row0 = warp * 16 + r;
    const int row1 = row0 + 8;
    const int i0 = q0 + row0;
    const int i1 = q0 + row1;

    float m0 = NEGBIG, l0 = 0.f;
    float m1 = NEGBIG, l1 = 0.f;
    float oc[8][4];
#pragma unroll
    for (int nt = 0; nt < 8; nt++)
#pragma unroll
        for (int i = 0; i < 4; i++) oc[nt][i] = 0.f;

    int jmin = q0 - WINDOW;
    if (jmin < 0) jmin = 0;

    for (int k0 = jmin; k0 < q0 + 128; k0 += 64) {
        __syncthreads();  // prior iteration's reads of ks/vts finished

        // ---- stage K tile [64 keys][64 d] ----
#pragma unroll
        for (int it = 0; it < 4; it++) {
            int f = tid + it * 256;
            int jj = f >> 4;
            int d = (f & 15) * 4;
            float4 v = *(const float4*)(Kb + (size_t)(k0 + jj) * (NGROUPS * DK) + d);
            uint4 t = make_uint4(f2tf32(v.x), f2tf32(v.y), f2tf32(v.z), f2tf32(v.w));
            *(uint4*)&ks[jj][d] = t;
        }
        // ---- stage V^T tile [64 d][64 keys] ----
#pragma unroll
        for (int it = 0; it < 4; it++) {
            int f = tid + it * 256;
            int jj = f & 63;
            int d = (f >> 6) * 4;
            float4 v = *(const float4*)(Vb + (size_t)(k0 + jj) * (NGROUPS * DK) + d);
            vts[d + 0][jj] = f2tf32(v.x);
            vts[d + 1][jj] = f2tf32(v.y);
            vts[d + 2][jj] = f2tf32(v.z);
            vts[d + 3][jj] = f2tf32(v.w);
        }
        __syncthreads();

        // ---- S = Q K^T: warp rows x 64 keys (8 n-tiles, 8 k-steps) ----
        float sc[8][4];
#pragma unroll
        for (int nt = 0; nt < 8; nt++)
#pragma unroll
            for (int i = 0; i < 4; i++) sc[nt][i] = 0.f;
#pragma unroll
        for (int kk = 0; kk < 8; kk++) {
            uint32_t a0 = qs[row0][kk * 8 + cl];
            uint32_t a1 = qs[row1][kk * 8 + cl];
            uint32_t a2 = qs[row0][kk * 8 + cl + 4];
            uint32_t a3 = qs[row1][kk * 8 + cl + 4];
#pragma unroll
            for (int nt = 0; nt < 8; nt++) {
                uint32_t b0 = ks[nt * 8 + r][kk * 8 + cl];
                uint32_t b1 = ks[nt * 8 + r][kk * 8 + cl + 4];
                mma_tf32(sc[nt][0], sc[nt][1], sc[nt][2], sc[nt][3],
                         a0, a1, a2, a3, b0, b1);
            }
        }

        // ---- mask + row max (warp-local, quad reduce) ----
        float rmax0 = NEGBIG, rmax1 = NEGBIG;
#pragma unroll
        for (int nt = 0; nt < 8; nt++) {
            int jc = k0 + nt * 8 + 2 * cl;
#pragma unroll
            for (int e = 0; e < 2; e++) {
                int j = jc + e;
                bool ok0 = (j <= i0) && (i0 - j <= WINDOW);
                bool ok1 = (j <= i1) && (i1 - j <= WINDOW);
                sc[nt][e]     = ok0 ? sc[nt][e]     : NEGBIG;
                sc[nt][e + 2] = ok1 ? sc[nt][e + 2] : NEGBIG;
                rmax0 = fmaxf(rmax0, sc[nt][e]);
                rmax1 = fmaxf(rmax1, sc[nt][e + 2]);
            }
        }
        rmax0 = fmaxf(rmax0, __shfl_xor_sync(FULLM, rmax0, 1));
        rmax0 = fmaxf(rmax0, __shfl_xor_sync(FULLM, rmax0, 2));
        rmax1 = fmaxf(rmax1, __shfl_xor_sync(FULLM, rmax1, 1));
        rmax1 = fmaxf(rmax1, __shfl_xor_sync(FULLM, rmax1, 2));

        float m_new0 = fmaxf(m0, rmax0);
        float m_new1 = fmaxf(m1, rmax1);
        float corr0 = __expf(m0 - m_new0);
        float corr1 = __expf(m1 - m_new1);

        // ---- exp + row sums ----
        float sum0 = 0.f, sum1 = 0.f;
#pragma unroll
        for (int nt = 0; nt < 8; nt++) {
            sc[nt][0] = __expf(sc[nt][0] - m_new0);
            sc[nt][1] = __expf(sc[nt][1] - m_new0);
            sc[nt][2] = __expf(sc[nt][2] - m_new1);
            sc[nt][3] = __expf(sc[nt][3] - m_new1);
            sum0 += sc[nt][0] + sc[nt][1];
            sum1 += sc[nt][2] + sc[nt][3];
        }
        sum0 += __shfl_xor_sync(FULLM, sum0, 1);
        sum0 += __shfl_xor_sync(FULLM, sum0, 2);
        sum1 += __shfl_xor_sync(FULLM, sum1, 1);
        sum1 += __shfl_xor_sync(FULLM, sum1, 2);

        l0 = l0 * corr0 + sum0;
        l1 = l1 * corr1 + sum1;
        m0 = m_new0;
        m1 = m_new1;

        // ---- rescale O accumulators ----
#pragma unroll
        for (int nt = 0; nt < 8; nt++) {
            oc[nt][0] *= corr0; oc[nt][1] *= corr0;
            oc[nt][2] *= corr1; oc[nt][3] *= corr1;
        }

        // ---- O += P V: convert C-frag P -> A-frag via quad shuffles ----
        const int qb = lane & ~3;       // quad base lane
        const int s0l = qb + (cl >> 1); // src lane for cols cl
        const int s1l = s0l + 2;        // src lane for cols cl+4
        const bool oddc = (cl & 1);
#pragma unroll
        for (int kk = 0; kk < 8; kk++) {
            float p0 = sc[kk][0], p1 = sc[kk][1];
            float p2 = sc[kk][2], p3 = sc[kk][3];
            float v00 = __shfl_sync(FULLM, p0, s0l);
            float v01 = __shfl_sync(FULLM, p1, s0l);
            float v20 = __shfl_sync(FULLM, p2, s0l);
            float v21 = __shfl_sync(FULLM, p3, s0l);
            float v00b = __shfl_sync(FULLM, p0, s1l);
            float v01b = __shfl_sync(FULLM, p1, s1l);
            float v20b = __shfl_sync(FULLM, p2, s1l);
            float v21b = __shfl_sync(FULLM, p3, s1l);
            uint32_t a0 = f2tf32(oddc ? v01  : v00);   // P[row0][cl]
            uint32_t a1 = f2tf32(oddc ? v21  : v20);   // P[row1][cl]
            uint32_t a2 = f2tf32(oddc ? v01b : v00b);  // P[row0][cl+4]
            uint32_t a3 = f2tf32(oddc ? v21b : v20b);  // P[row1][cl+4]
#pragma unroll
            for (int nt = 0; nt < 8; nt++) {
                uint32_t b0 = vts[nt * 8 + r][kk * 8 + cl];
                uint32_t b1 = vts[nt * 8 + r][kk * 8 + cl + 4];
                mma_tf32(oc[nt][0], oc[nt][1], oc[nt][2], oc[nt][3],
                         a0, a1, a2, a3, b0, b1);
            }
        }
    }

    // ---- epilogue ----
    float inv0 = 1.0f / l0;
    float inv1 = 1.0f / l1;
    float* Ob0 = O + ((size_t)(b * TLEN + i0)) * DMODEL + h * DK;
    float* Ob1 = O + ((size_t)(b * TLEN + i1)) * DMODEL + h * DK;
#pragma unroll
    for (int nt = 0; nt < 8; nt++) {
        int dcol = nt * 8 + 2 * cl;
        *(float2*)(Ob0 + dcol) = make_float2(oc[nt][0] * inv0, oc[nt][1] * inv0);
        *(float2*)(Ob1 + dcol) = make_float2(oc[nt][2] * inv1, oc[nt][3] * inv1);
    }
}

// =======================================================================
// Host launcher
// =======================================================================
extern "C" void kernel_launch(void* const* d_in, const int* in_sizes, int n_in,
                              void* d_out, int out_size)
{
    const float* x  = (const float*)d_in[0];
    const float* WQ = (const float*)d_in[1];
    const float* WK = (const float*)d_in[2];
    const float* WV = (const float*)d_in[3];
    const float* WO = (const float*)d_in[4];
    const int* tpos = (const int*)d_in[5];
    float* out = (float*)d_out;

    float *Qp, *Kp, *Vp, *Ap;
    cudaGetSymbolAddress((void**)&Qp, g_Q);
    cudaGetSymbolAddress((void**)&Kp, g_K);
    cudaGetSymbolAddress((void**)&Vp, g_V);
    cudaGetSymbolAddress((void**)&Ap, g_ATT);

    const int gemm_smem = (2 * BM * SPAD + 2 * BN * SPAD) * 4;   // 55296 B
    const int attn_smem = (128 * 68 + 64 * 68 + 64 * 68) * 4;    // 69632 B
    static bool attr_done = false;
    if (!attr_done) {
        cudaFuncSetAttribute(gemm_tf32, cudaFuncAttributeMaxDynamicSharedMemorySize, gemm_smem);
        cudaFuncSetAttribute(attn_mma_kernel, cudaFuncAttributeMaxDynamicSharedMemorySize, attn_smem);
        attr_done = true;
    }

    // 1. Q projection
    gemm_tf32<<<dim3(DMODEL / BN, MTOK / BM, 1), 256, gemm_smem>>>(
        x, WQ, WQ, Qp, Qp, MTOK, DMODEL, DMODEL);
    // 1b. K and V projections fused
    gemm_tf32<<<dim3((NGROUPS * DK) / BN, MTOK / BM, 2), 256, gemm_smem>>>(
        x, WK, WV, Kp, Vp, MTOK, NGROUPS * DK, DMODEL);

    // 2. RoPE (Q and K in one launch)
    {
        int total = NQ_ROPE + NK_ROPE;
        rope_all<<<(total + 255) / 256, 256>>>(Qp, Kp, tpos);
    }

    // 3. Attention (128q x 64k tensor-core tiles)
    attn_mma_kernel<<<dim3(TLEN / 128, NHEADS, BATCH), 256, attn_smem>>>(Qp, Kp, Vp, Ap);

    // 4. Output projection
    gemm_tf32<<<dim3(DMODEL / BN, MTOK / BM, 1), 256, gemm_smem>>>(
        Ap, WO, WO, out, out, MTOK, DMODEL, DMODEL);
}